// round 2
// baseline (speedup 1.0000x reference)
#include <cuda_runtime.h>
#include <cuda_bf16.h>
#include <mma.h>

using namespace nvcuda;

#define BATCH 64
#define SEQ   512
#define HID   512
#define GATES 2048      // 4*HID
#define KIN   96        // 64 + 32
#define ODIM  128

#define NB_SCAN 128
#define NT_SCAN 128

// ---------------- static device scratch (no allocations allowed) ----------------
__device__ float g_xproj[(size_t)BATCH * SEQ * GATES];   // 256 MB, reused for layer0 then layer1
__device__ float g_h0s[(size_t)BATCH * SEQ * HID];       // 64 MB, layer-0 hidden history
__device__ float g_xcat[(size_t)BATCH * SEQ * KIN];      // 12 MB
__device__ float g_Wih0p[GATES * KIN];
__device__ float g_Whh0p[GATES * HID];
__device__ float g_Wih1p[GATES * HID];
__device__ float g_Whh1p[GATES * HID];
__device__ float g_biasP[2][GATES];
__device__ float g_hbuf[2][BATCH * HID];                 // ping-pong hidden state
__device__ float g_cst[BATCH * HID];                     // cell state
__device__ unsigned g_bar_count;
__device__ unsigned g_bar_gen;

// ---------------- grid barrier (sense via generation counter) ----------------
__device__ __forceinline__ void grid_barrier()
{
    __syncthreads();
    if (threadIdx.x == 0) {
        __threadfence();  // make my h/c writes visible before signaling
        unsigned gen = atomicAdd(&g_bar_gen, 0u);
        unsigned arrived = atomicAdd(&g_bar_count, 1u);
        if (arrived == NB_SCAN - 1) {
            atomicExch(&g_bar_count, 0u);
            __threadfence();
            atomicAdd(&g_bar_gen, 1u);
        } else {
            while (atomicAdd(&g_bar_gen, 0u) == gen) { __nanosleep(32); }
        }
        // gpu-scope fence -> CCTL.IVALL: invalidate this SM's L1D so the
        // subsequent loads of h (written by other SMs) are not stale.
        __threadfence();
    }
    __syncthreads();
}

__device__ __forceinline__ float sigm(float x) { return 1.0f / (1.0f + expf(-x)); }

// ---------------- prep: concat input, permute weights so gates interleave ----------------
// col' = 4*u + gate  <->  original row r = gate*HID + u
__global__ void prep_kernel(const float* __restrict__ prim, const float* __restrict__ aux,
                            const float* __restrict__ Wih0, const float* __restrict__ Whh0,
                            const float* __restrict__ bih0, const float* __restrict__ bhh0,
                            const float* __restrict__ Wih1, const float* __restrict__ Whh1,
                            const float* __restrict__ bih1, const float* __restrict__ bhh1)
{
    size_t tid = (size_t)blockIdx.x * blockDim.x + threadIdx.x;
    size_t nth = (size_t)gridDim.x * blockDim.x;

    for (size_t i = tid; i < (size_t)BATCH * SEQ * KIN; i += nth) {
        int k = (int)(i % KIN);
        size_t bt = i / KIN;
        int b = (int)(bt / SEQ);
        g_xcat[i] = (k < 64) ? prim[bt * 64 + k] : aux[b * 32 + (k - 64)];
    }
    for (size_t i = tid; i < (size_t)GATES * HID; i += nth) {
        int k  = (int)(i % HID);
        int cp = (int)(i / HID);
        int u = cp >> 2, gi = cp & 3;
        size_t r = (size_t)(gi * HID + u) * HID + k;
        g_Whh0p[i] = Whh0[r];
        g_Whh1p[i] = Whh1[r];
        g_Wih1p[i] = Wih1[r];
    }
    for (size_t i = tid; i < (size_t)GATES * KIN; i += nth) {
        int k  = (int)(i % KIN);
        int cp = (int)(i / KIN);
        int u = cp >> 2, gi = cp & 3;
        g_Wih0p[i] = Wih0[(size_t)(gi * HID + u) * KIN + k];
    }
    for (size_t i = tid; i < GATES; i += nth) {
        int u = (int)(i >> 2), gi = (int)(i & 3);
        int r = gi * HID + u;
        g_biasP[0][i] = bih0[r] + bhh0[r];
        g_biasP[1][i] = bih1[r] + bhh1[r];
    }
}

// ---------------- big parallel GEMM (tf32 wmma): C[32768 x 2048] = A[M x K] @ Wp^T ----------------
// phase 0: A = g_xcat   (K=96),  B = g_Wih0p
// phase 1: A = g_h0s    (K=512), B = g_Wih1p
#define GT_M 128
#define GT_N 128
#define KCHUNK 16
#define SPAD 20

__global__ void __launch_bounds__(256) gemm_tf32(int phase)
{
    __shared__ float As[GT_M * SPAD];
    __shared__ float Bs[GT_N * SPAD];

    const float* A  = phase ? g_h0s   : g_xcat;
    const float* Bm = phase ? g_Wih1p : g_Wih0p;
    const int K     = phase ? HID     : KIN;

    int tn = blockIdx.x;           // 0..15
    int tm = blockIdx.y;           // 0..255
    int tid = threadIdx.x;
    int wid = tid >> 5;
    int wm = wid >> 2, wn = wid & 3;   // warp grid 2 x 4, warp tile 64 x 32

    wmma::fragment<wmma::accumulator, 16, 16, 8, float> acc[4][2];
#pragma unroll
    for (int i = 0; i < 4; i++)
#pragma unroll
        for (int j = 0; j < 2; j++) wmma::fill_fragment(acc[i][j], 0.0f);

    const float* Abase = A  + (size_t)tm * GT_M * K;
    const float* Bbase = Bm + (size_t)tn * GT_N * K;

    for (int k0 = 0; k0 < K; k0 += KCHUNK) {
        __syncthreads();
#pragma unroll
        for (int s = tid; s < GT_M * 4; s += 256) {
            int m = s >> 2, q = s & 3;
            *(float4*)&As[m * SPAD + q * 4] = *(const float4*)&Abase[(size_t)m * K + k0 + q * 4];
            *(float4*)&Bs[m * SPAD + q * 4] = *(const float4*)&Bbase[(size_t)m * K + k0 + q * 4];
        }
        __syncthreads();
#pragma unroll
        for (int ks = 0; ks < 2; ks++) {
            wmma::fragment<wmma::matrix_b, 16, 16, 8, wmma::precision::tf32, wmma::col_major> bf[2];
#pragma unroll
            for (int j = 0; j < 2; j++) {
                wmma::load_matrix_sync(bf[j], &Bs[(wn * 32 + j * 16) * SPAD + ks * 8], SPAD);
#pragma unroll
                for (int e = 0; e < bf[j].num_elements; e++)
                    bf[j].x[e] = wmma::__float_to_tf32(bf[j].x[e]);
            }
#pragma unroll
            for (int i = 0; i < 4; i++) {
                wmma::fragment<wmma::matrix_a, 16, 16, 8, wmma::precision::tf32, wmma::row_major> af;
                wmma::load_matrix_sync(af, &As[(wm * 64 + i * 16) * SPAD + ks * 8], SPAD);
#pragma unroll
                for (int e = 0; e < af.num_elements; e++)
                    af.x[e] = wmma::__float_to_tf32(af.x[e]);
#pragma unroll
                for (int j = 0; j < 2; j++) wmma::mma_sync(acc[i][j], af, bf[j], acc[i][j]);
            }
        }
    }
#pragma unroll
    for (int i = 0; i < 4; i++)
#pragma unroll
        for (int j = 0; j < 2; j++) {
            int gm = tm * GT_M + wm * 64 + i * 16;
            int gn = tn * GT_N + wn * 32 + j * 16;
            wmma::store_matrix_sync(&g_xproj[(size_t)gm * GATES + gn], acc[i][j], GATES,
                                    wmma::mem_row_major);
        }
}

// ---------------- persistent recurrent scan (one layer) ----------------
// 128 CTAs x 128 threads. CTA c owns hidden units [4c, 4c+4) = gate cols [16c, 16c+16).
// warp w handles batch rows [16w, 16w+16). Full K=512 per warp (64 k-steps of 8).
__global__ void __launch_bounds__(NT_SCAN) scan_tf32(int layer)
{
    __shared__ float sg[4 * 256];
    const int c   = blockIdx.x;
    const int tid = threadIdx.x;
    const int w   = tid >> 5;

    const float* Wp    = layer ? g_Whh1p : g_Whh0p;
    const float* biasP = g_biasP[layer];

    // zero state (fresh every launch), then make it globally visible
    for (int i = blockIdx.x * NT_SCAN + tid; i < BATCH * HID; i += NB_SCAN * NT_SCAN) {
        g_cst[i] = 0.0f;
        g_hbuf[0][i] = 0.0f;
    }
    grid_barrier();

    const float* Wbase = Wp + (size_t)c * 16 * HID;

    for (int t = 0; t < SEQ; t++) {
        const float* hread  = g_hbuf[t & 1];
        float*       hwrite = g_hbuf[(t & 1) ^ 1];

        wmma::fragment<wmma::accumulator, 16, 16, 8, float> acc0, acc1;
        wmma::fill_fragment(acc0, 0.0f);
        wmma::fill_fragment(acc1, 0.0f);
        const float* Arow = hread + (size_t)w * 16 * HID;

#pragma unroll 4
        for (int ks = 0; ks < 64; ks += 2) {
            wmma::fragment<wmma::matrix_a, 16, 16, 8, wmma::precision::tf32, wmma::row_major> af0, af1;
            wmma::fragment<wmma::matrix_b, 16, 16, 8, wmma::precision::tf32, wmma::col_major> bf0, bf1;
            wmma::load_matrix_sync(af0, Arow + ks * 8, HID);
            wmma::load_matrix_sync(bf0, Wbase + ks * 8, HID);
            wmma::load_matrix_sync(af1, Arow + ks * 8 + 8, HID);
            wmma::load_matrix_sync(bf1, Wbase + ks * 8 + 8, HID);
#pragma unroll
            for (int e = 0; e < 4; e++) {
                af0.x[e] = wmma::__float_to_tf32(af0.x[e]);
                af1.x[e] = wmma::__float_to_tf32(af1.x[e]);
                bf0.x[e] = wmma::__float_to_tf32(bf0.x[e]);
                bf1.x[e] = wmma::__float_to_tf32(bf1.x[e]);
            }
            wmma::mma_sync(acc0, af0, bf0, acc0);
            wmma::mma_sync(acc1, af1, bf1, acc1);
        }
#pragma unroll
        for (int e = 0; e < acc0.num_elements; e++) acc0.x[e] += acc1.x[e];
        wmma::store_matrix_sync(&sg[w * 256], acc0, 16, wmma::mem_row_major);
        __syncthreads();

        // elementwise LSTM cell: 256 (b, unit) pairs, 2 per thread
#pragma unroll
        for (int rep = 0; rep < 2; rep++) {
            int p  = tid + rep * NT_SCAN;
            int b  = p >> 2;
            int ul = p & 3;
            const float* gp = &sg[(b >> 4) * 256 + (b & 15) * 16 + ul * 4];
            float4 xp = *(const float4*)(g_xproj + ((size_t)(b * SEQ + t)) * GATES + c * 16 + ul * 4);
            float4 bb = *(const float4*)(biasP + c * 16 + ul * 4);
            float pi = gp[0] + xp.x + bb.x;
            float pf = gp[1] + xp.y + bb.y;
            float pg = gp[2] + xp.z + bb.z;
            float po = gp[3] + xp.w + bb.w;
            float ig = sigm(pi), fg = sigm(pf), gg = tanhf(pg), og = sigm(po);
            int u   = c * 4 + ul;
            int idx = b * HID + u;
            float cn = fg * g_cst[idx] + ig * gg;
            g_cst[idx] = cn;
            float hv = og * tanhf(cn);
            hwrite[idx] = hv;
            if (layer == 0) g_h0s[((size_t)(b * SEQ + t)) * HID + u] = hv;
        }
        grid_barrier();
    }
}

// ---------------- output projection: out[b,o] = h_last[b,:] . W_out[o,:] + b_out[o] ----------------
__global__ void out_kernel(const float* __restrict__ Wout, const float* __restrict__ bout,
                           float* __restrict__ out)
{
    int b = blockIdx.x;    // 64
    int o = threadIdx.x;   // 128
    const float* h  = g_hbuf[0] + b * HID;   // SEQ even -> final h lands in buffer 0
    const float* wr = Wout + o * HID;
    float acc = bout[o];
#pragma unroll 8
    for (int u = 0; u < HID; u++) acc = fmaf(h[u], wr[u], acc);
    out[b * ODIM + o] = acc;
}

// ---------------- launch ----------------
extern "C" void kernel_launch(void* const* d_in, const int* in_sizes, int n_in,
                              void* d_out, int out_size)
{
    (void)in_sizes; (void)n_in; (void)out_size;
    const float* prim = (const float*)d_in[0];
    const float* aux  = (const float*)d_in[1];
    const float* Wih0 = (const float*)d_in[2];
    const float* Whh0 = (const float*)d_in[3];
    const float* bih0 = (const float*)d_in[4];
    const float* bhh0 = (const float*)d_in[5];
    const float* Wih1 = (const float*)d_in[6];
    const float* Whh1 = (const float*)d_in[7];
    const float* bih1 = (const float*)d_in[8];
    const float* bhh1 = (const float*)d_in[9];
    const float* Wout = (const float*)d_in[10];
    const float* bout = (const float*)d_in[11];
    float* out = (float*)d_out;

    prep_kernel<<<1024, 256>>>(prim, aux, Wih0, Whh0, bih0, bhh0, Wih1, Whh1, bih1, bhh1);
    gemm_tf32<<<dim3(16, 256), 256>>>(0);    // x_proj0
    scan_tf32<<<NB_SCAN, NT_SCAN>>>(0);      // layer-0 scan (writes g_h0s)
    gemm_tf32<<<dim3(16, 256), 256>>>(1);    // x_proj1 from h0s
    scan_tf32<<<NB_SCAN, NT_SCAN>>>(1);      // layer-1 scan
    out_kernel<<<BATCH, ODIM>>>(Wout, bout, out);
}

// round 3
// speedup vs baseline: 1.1819x; 1.1819x over previous
#include <cuda_runtime.h>
#include <cuda_bf16.h>
#include <mma.h>

using namespace nvcuda;

#define BATCH 64
#define SEQ   512
#define HID   512
#define GATES 2048      // 4*HID
#define KIN   96        // 64 + 32
#define ODIM  128

#define NB_SCAN 64
#define NT_SCAN 256
#define CCOLS   32      // gate cols per CTA
#define WPAD    520     // 512 + 8 padding (bank-conflict-free wmma B loads)
#define WS_FLOATS (CCOLS * WPAD)          // 16640
#define SG_FLOATS (BATCH * CCOLS)         // 2048
#define SCAN_SMEM_BYTES ((WS_FLOATS + SG_FLOATS) * 4)

// ---------------- static device scratch (no allocations allowed) ----------------
__device__ float g_xproj[(size_t)BATCH * SEQ * GATES];   // reused for layer0 then layer1
__device__ float g_h0s[(size_t)BATCH * SEQ * HID];       // layer-0 hidden history
__device__ float g_xcat[(size_t)BATCH * SEQ * KIN];
__device__ float g_Wih0p[GATES * KIN];
__device__ float g_Whh0p[GATES * HID];
__device__ float g_Wih1p[GATES * HID];
__device__ float g_Whh1p[GATES * HID];
__device__ float g_biasP[2][GATES];
__device__ float g_hbuf[2][BATCH * HID];                 // ping-pong hidden state
__device__ float g_cst[BATCH * HID];                     // cell state
__device__ unsigned g_bar_count;
__device__ unsigned g_bar_gen;

// ---------------- grid barrier (sense via generation counter) ----------------
__device__ __forceinline__ void grid_barrier()
{
    __syncthreads();
    if (threadIdx.x == 0) {
        __threadfence();  // release: my h/c stores visible before signaling
        unsigned gen = atomicAdd(&g_bar_gen, 0u);
        unsigned arrived = atomicAdd(&g_bar_count, 1u);
        if (arrived == NB_SCAN - 1) {
            atomicExch(&g_bar_count, 0u);
            __threadfence();
            atomicAdd(&g_bar_gen, 1u);
        } else {
            while (atomicAdd(&g_bar_gen, 0u) == gen) { __nanosleep(16); }
        }
        // acquire: invalidate stale L1 lines before reading other SMs' h.
        // (W lives in SMEM so this no longer forces weight refetches.)
        __threadfence();
    }
    __syncthreads();
}

__device__ __forceinline__ float sigm(float x) { return 1.0f / (1.0f + expf(-x)); }

// ---------------- prep: concat input, permute weights so gates interleave ----------------
// col' = 4*u + gate  <->  original row r = gate*HID + u
__global__ void prep_kernel(const float* __restrict__ prim, const float* __restrict__ aux,
                            const float* __restrict__ Wih0, const float* __restrict__ Whh0,
                            const float* __restrict__ bih0, const float* __restrict__ bhh0,
                            const float* __restrict__ Wih1, const float* __restrict__ Whh1,
                            const float* __restrict__ bih1, const float* __restrict__ bhh1)
{
    size_t tid = (size_t)blockIdx.x * blockDim.x + threadIdx.x;
    size_t nth = (size_t)gridDim.x * blockDim.x;

    for (size_t i = tid; i < (size_t)BATCH * SEQ * KIN; i += nth) {
        int k = (int)(i % KIN);
        size_t bt = i / KIN;
        int b = (int)(bt / SEQ);
        g_xcat[i] = (k < 64) ? prim[bt * 64 + k] : aux[b * 32 + (k - 64)];
    }
    for (size_t i = tid; i < (size_t)GATES * HID; i += nth) {
        int k  = (int)(i % HID);
        int cp = (int)(i / HID);
        int u = cp >> 2, gi = cp & 3;
        size_t r = (size_t)(gi * HID + u) * HID + k;
        g_Whh0p[i] = Whh0[r];
        g_Whh1p[i] = Whh1[r];
        g_Wih1p[i] = Wih1[r];
    }
    for (size_t i = tid; i < (size_t)GATES * KIN; i += nth) {
        int k  = (int)(i % KIN);
        int cp = (int)(i / KIN);
        int u = cp >> 2, gi = cp & 3;
        g_Wih0p[i] = Wih0[(size_t)(gi * HID + u) * KIN + k];
    }
    for (size_t i = tid; i < GATES; i += nth) {
        int u = (int)(i >> 2), gi = (int)(i & 3);
        int r = gi * HID + u;
        g_biasP[0][i] = bih0[r] + bhh0[r];
        g_biasP[1][i] = bih1[r] + bhh1[r];
    }
}

// ---------------- big parallel GEMM (tf32 wmma): C[32768 x 2048] = A[M x K] @ Wp^T ----------------
#define GT_M 128
#define GT_N 128
#define KCHUNK 16
#define SPAD 20

__global__ void __launch_bounds__(256) gemm_tf32(int phase)
{
    __shared__ float As[GT_M * SPAD];
    __shared__ float Bs[GT_N * SPAD];

    const float* A  = phase ? g_h0s   : g_xcat;
    const float* Bm = phase ? g_Wih1p : g_Wih0p;
    const int K     = phase ? HID     : KIN;

    int tn = blockIdx.x;
    int tm = blockIdx.y;
    int tid = threadIdx.x;
    int wid = tid >> 5;
    int wm = wid >> 2, wn = wid & 3;

    wmma::fragment<wmma::accumulator, 16, 16, 8, float> acc[4][2];
#pragma unroll
    for (int i = 0; i < 4; i++)
#pragma unroll
        for (int j = 0; j < 2; j++) wmma::fill_fragment(acc[i][j], 0.0f);

    const float* Abase = A  + (size_t)tm * GT_M * K;
    const float* Bbase = Bm + (size_t)tn * GT_N * K;

    for (int k0 = 0; k0 < K; k0 += KCHUNK) {
        __syncthreads();
#pragma unroll
        for (int s = tid; s < GT_M * 4; s += 256) {
            int m = s >> 2, q = s & 3;
            *(float4*)&As[m * SPAD + q * 4] = *(const float4*)&Abase[(size_t)m * K + k0 + q * 4];
            *(float4*)&Bs[m * SPAD + q * 4] = *(const float4*)&Bbase[(size_t)m * K + k0 + q * 4];
        }
        __syncthreads();
#pragma unroll
        for (int ks = 0; ks < 2; ks++) {
            wmma::fragment<wmma::matrix_b, 16, 16, 8, wmma::precision::tf32, wmma::col_major> bf[2];
#pragma unroll
            for (int j = 0; j < 2; j++) {
                wmma::load_matrix_sync(bf[j], &Bs[(wn * 32 + j * 16) * SPAD + ks * 8], SPAD);
#pragma unroll
                for (int e = 0; e < bf[j].num_elements; e++)
                    bf[j].x[e] = wmma::__float_to_tf32(bf[j].x[e]);
            }
#pragma unroll
            for (int i = 0; i < 4; i++) {
                wmma::fragment<wmma::matrix_a, 16, 16, 8, wmma::precision::tf32, wmma::row_major> af;
                wmma::load_matrix_sync(af, &As[(wm * 64 + i * 16) * SPAD + ks * 8], SPAD);
#pragma unroll
                for (int e = 0; e < af.num_elements; e++)
                    af.x[e] = wmma::__float_to_tf32(af.x[e]);
#pragma unroll
                for (int j = 0; j < 2; j++) wmma::mma_sync(acc[i][j], af, bf[j], acc[i][j]);
            }
        }
    }
#pragma unroll
    for (int i = 0; i < 4; i++)
#pragma unroll
        for (int j = 0; j < 2; j++) {
            int gm = tm * GT_M + wm * 64 + i * 16;
            int gn = tn * GT_N + wn * 32 + j * 16;
            wmma::store_matrix_sync(&g_xproj[(size_t)gm * GATES + gn], acc[i][j], GATES,
                                    wmma::mem_row_major);
        }
}

// ---------------- persistent recurrent scan (one layer) ----------------
// 64 CTAs x 256 threads. CTA c owns hidden units [8c, 8c+8) = gate cols [32c, 32c+32).
// W slice (32 x 512) is staged in SMEM once. Warp grid 4(m) x 2(n): warp tile 16 x 16,
// full K=512 per warp as 2 independent accumulator chains.
__global__ void __launch_bounds__(NT_SCAN) scan_tf32(int layer)
{
    extern __shared__ float smem[];
    float* Ws = smem;                 // [CCOLS][WPAD]
    float* sg = smem + WS_FLOATS;     // [8 warps][16*16]

    const int c   = blockIdx.x;
    const int tid = threadIdx.x;
    const int w   = tid >> 5;
    const int wm  = w >> 1, wn = w & 1;

    const float* Wp    = layer ? g_Whh1p : g_Whh0p;
    const float* biasP = g_biasP[layer];

    // stage W slice into smem (once). rows: gate cols c*32+n, padded stride WPAD.
    {
        const float* Wg = Wp + (size_t)c * CCOLS * HID;
#pragma unroll
        for (int idx = tid; idx < CCOLS * (HID / 4); idx += NT_SCAN) {
            int n = idx >> 7, q = idx & 127;
            *(float4*)&Ws[n * WPAD + q * 4] = *(const float4*)&Wg[(size_t)n * HID + q * 4];
        }
    }

    // zero state (fresh every launch)
    for (int i = blockIdx.x * NT_SCAN + tid; i < BATCH * HID; i += NB_SCAN * NT_SCAN) {
        g_cst[i] = 0.0f;
        g_hbuf[0][i] = 0.0f;
    }
    grid_barrier();

    for (int t = 0; t < SEQ; t++) {
        const float* hread  = g_hbuf[t & 1];
        float*       hwrite = g_hbuf[(t & 1) ^ 1];

        wmma::fragment<wmma::accumulator, 16, 16, 8, float> acc0, acc1;
        wmma::fill_fragment(acc0, 0.0f);
        wmma::fill_fragment(acc1, 0.0f);
        const float* Arow = hread + (size_t)wm * 16 * HID;
        const float* Bcol = &Ws[wn * 16 * WPAD];

#pragma unroll 8
        for (int ks = 0; ks < 64; ks += 2) {
            wmma::fragment<wmma::matrix_a, 16, 16, 8, wmma::precision::tf32, wmma::row_major> af0, af1;
            wmma::fragment<wmma::matrix_b, 16, 16, 8, wmma::precision::tf32, wmma::col_major> bf0, bf1;
            wmma::load_matrix_sync(af0, Arow + ks * 8, HID);
            wmma::load_matrix_sync(af1, Arow + ks * 8 + 8, HID);
            wmma::load_matrix_sync(bf0, Bcol + ks * 8, WPAD);
            wmma::load_matrix_sync(bf1, Bcol + ks * 8 + 8, WPAD);
#pragma unroll
            for (int e = 0; e < 4; e++) {
                af0.x[e] = wmma::__float_to_tf32(af0.x[e]);
                af1.x[e] = wmma::__float_to_tf32(af1.x[e]);
                bf0.x[e] = wmma::__float_to_tf32(bf0.x[e]);
                bf1.x[e] = wmma::__float_to_tf32(bf1.x[e]);
            }
            wmma::mma_sync(acc0, af0, bf0, acc0);
            wmma::mma_sync(acc1, af1, bf1, acc1);
        }
#pragma unroll
        for (int e = 0; e < acc0.num_elements; e++) acc0.x[e] += acc1.x[e];
        wmma::store_matrix_sync(&sg[w * 256], acc0, 16, wmma::mem_row_major);
        __syncthreads();

        // elementwise LSTM cell: 512 (b, unit) pairs, 2 per thread (each = 4 gates)
#pragma unroll
        for (int rep = 0; rep < 2; rep++) {
            int p  = tid + rep * NT_SCAN;
            int b  = p >> 3;
            int ul = p & 7;
            int gc = ul * 4;                        // local gate col of the i-gate
            const float* gp = &sg[((b >> 4) * 2 + (gc >> 4)) * 256 + (b & 15) * 16 + (gc & 15)];
            float4 xp = *(const float4*)(g_xproj + ((size_t)(b * SEQ + t)) * GATES + c * CCOLS + gc);
            float4 bb = *(const float4*)(biasP + c * CCOLS + gc);
            float pi = gp[0] + xp.x + bb.x;
            float pf = gp[1] + xp.y + bb.y;
            float pg = gp[2] + xp.z + bb.z;
            float po = gp[3] + xp.w + bb.w;
            float ig = sigm(pi), fg = sigm(pf), gg = tanhf(pg), og = sigm(po);
            int u   = c * 8 + ul;
            int idx = b * HID + u;
            float cn = fg * g_cst[idx] + ig * gg;
            g_cst[idx] = cn;
            float hv = og * tanhf(cn);
            hwrite[idx] = hv;
            if (layer == 0) g_h0s[((size_t)(b * SEQ + t)) * HID + u] = hv;
        }
        grid_barrier();
    }
}

// ---------------- output projection ----------------
__global__ void out_kernel(const float* __restrict__ Wout, const float* __restrict__ bout,
                           float* __restrict__ out)
{
    int b = blockIdx.x;
    int o = threadIdx.x;
    const float* h  = g_hbuf[0] + b * HID;   // SEQ even -> final h in buffer 0
    const float* wr = Wout + o * HID;
    float acc = bout[o];
#pragma unroll 8
    for (int u = 0; u < HID; u++) acc = fmaf(h[u], wr[u], acc);
    out[b * ODIM + o] = acc;
}

// ---------------- launch ----------------
extern "C" void kernel_launch(void* const* d_in, const int* in_sizes, int n_in,
                              void* d_out, int out_size)
{
    (void)in_sizes; (void)n_in; (void)out_size;
    const float* prim = (const float*)d_in[0];
    const float* aux  = (const float*)d_in[1];
    const float* Wih0 = (const float*)d_in[2];
    const float* Whh0 = (const float*)d_in[3];
    const float* bih0 = (const float*)d_in[4];
    const float* bhh0 = (const float*)d_in[5];
    const float* Wih1 = (const float*)d_in[6];
    const float* Whh1 = (const float*)d_in[7];
    const float* bih1 = (const float*)d_in[8];
    const float* bhh1 = (const float*)d_in[9];
    const float* Wout = (const float*)d_in[10];
    const float* bout = (const float*)d_in[11];
    float* out = (float*)d_out;

    static bool attr_set = false;
    if (!attr_set) {
        cudaFuncSetAttribute(scan_tf32, cudaFuncAttributeMaxDynamicSharedMemorySize,
                             SCAN_SMEM_BYTES);
        attr_set = true;
    }

    prep_kernel<<<1024, 256>>>(prim, aux, Wih0, Whh0, bih0, bhh0, Wih1, Whh1, bih1, bhh1);
    gemm_tf32<<<dim3(16, 256), 256>>>(0);                        // x_proj0
    scan_tf32<<<NB_SCAN, NT_SCAN, SCAN_SMEM_BYTES>>>(0);         // layer-0 scan
    gemm_tf32<<<dim3(16, 256), 256>>>(1);                        // x_proj1
    scan_tf32<<<NB_SCAN, NT_SCAN, SCAN_SMEM_BYTES>>>(1);         // layer-1 scan
    out_kernel<<<BATCH, ODIM>>>(Wout, bout, out);
}

// round 4
// speedup vs baseline: 2.7873x; 2.3584x over previous
#include <cuda_runtime.h>
#include <cuda_bf16.h>
#include <mma.h>

using namespace nvcuda;

#define BATCH 64
#define SEQ   512
#define HID   512
#define GATES 2048      // 4*HID
#define KIN   96        // 64 + 32
#define ODIM  128

#define NB_SCAN 64
#define NT_SCAN 256
#define CCOLS   32      // gate cols per CTA
#define APAD    532     // 532 mod 32 = 20 -> conflict-free 8-row wmma access, %4==0 for float4
#define WPAD    532
#define SGP     36      // sg row pad
#define A_FLOATS (64 * APAD)
#define W_FLOATS (CCOLS * WPAD)
#define SCAN_SMEM_BYTES ((A_FLOATS + W_FLOATS) * 4)   // 204,288 B

// ---------------- static device scratch ----------------
__device__ float g_xproj[(size_t)BATCH * SEQ * GATES];
__device__ float g_h0s[(size_t)BATCH * SEQ * HID];
__device__ float g_xcat[(size_t)BATCH * SEQ * KIN];
__device__ float g_Wih0p[GATES * KIN];
__device__ float g_Whh0p[GATES * HID];
__device__ float g_Wih1p[GATES * HID];
__device__ float g_Whh1p[GATES * HID];
__device__ float g_biasP[2][GATES];
__device__ float g_hbuf[2][BATCH * HID];
__device__ unsigned g_arrive;   // monotonic arrival counter
__device__ unsigned g_epoch;    // monotonic completed-round counter

// ---------------- release/acquire primitives ----------------
__device__ __forceinline__ unsigned ld_acquire_gpu(unsigned* p) {
    unsigned v;
    asm volatile("ld.acquire.gpu.global.u32 %0, [%1];" : "=r"(v) : "l"(p) : "memory");
    return v;
}
__device__ __forceinline__ unsigned atom_add_release_gpu(unsigned* p, unsigned v) {
    unsigned old;
    asm volatile("atom.release.gpu.global.add.u32 %0, [%1], %2;"
                 : "=r"(old) : "l"(p), "r"(v) : "memory");
    return old;
}
__device__ __forceinline__ void st_release_gpu(unsigned* p, unsigned v) {
    asm volatile("st.release.gpu.global.u32 [%0], %1;" :: "l"(p), "r"(v) : "memory");
}

// monotonic-epoch grid barrier. round is absolute (continues across launches).
__device__ __forceinline__ void grid_barrier_round(unsigned round) {
    __syncthreads();
    if (threadIdx.x == 0) {
        unsigned prev = atom_add_release_gpu(&g_arrive, 1u);
        if (prev + 1u == round * NB_SCAN) {
            st_release_gpu(&g_epoch, round);
        } else {
            while ((int)(ld_acquire_gpu(&g_epoch) - round) < 0) { }
        }
    }
    __syncthreads();
}

__device__ __forceinline__ float sigm(float x) { return 1.0f / (1.0f + expf(-x)); }

__device__ __forceinline__ float4 ldcg4(const float* p) {
    return __ldcg((const float4*)p);
}

// ---------------- prep: concat input, permute weights (col' = 4u+gate) ----------------
__global__ void prep_kernel(const float* __restrict__ prim, const float* __restrict__ aux,
                            const float* __restrict__ Wih0, const float* __restrict__ Whh0,
                            const float* __restrict__ bih0, const float* __restrict__ bhh0,
                            const float* __restrict__ Wih1, const float* __restrict__ Whh1,
                            const float* __restrict__ bih1, const float* __restrict__ bhh1)
{
    size_t tid = (size_t)blockIdx.x * blockDim.x + threadIdx.x;
    size_t nth = (size_t)gridDim.x * blockDim.x;

    for (size_t i = tid; i < (size_t)BATCH * SEQ * KIN; i += nth) {
        int k = (int)(i % KIN);
        size_t bt = i / KIN;
        int b = (int)(bt / SEQ);
        g_xcat[i] = (k < 64) ? prim[bt * 64 + k] : aux[b * 32 + (k - 64)];
    }
    for (size_t i = tid; i < (size_t)GATES * HID; i += nth) {
        int k  = (int)(i % HID);
        int cp = (int)(i / HID);
        int u = cp >> 2, gi = cp & 3;
        size_t r = (size_t)(gi * HID + u) * HID + k;
        g_Whh0p[i] = Whh0[r];
        g_Whh1p[i] = Whh1[r];
        g_Wih1p[i] = Wih1[r];
    }
    for (size_t i = tid; i < (size_t)GATES * KIN; i += nth) {
        int k  = (int)(i % KIN);
        int cp = (int)(i / KIN);
        int u = cp >> 2, gi = cp & 3;
        g_Wih0p[i] = Wih0[(size_t)(gi * HID + u) * KIN + k];
    }
    for (size_t i = tid; i < GATES; i += nth) {
        int u = (int)(i >> 2), gi = (int)(i & 3);
        int r = gi * HID + u;
        g_biasP[0][i] = bih0[r] + bhh0[r];
        g_biasP[1][i] = bih1[r] + bhh1[r];
    }
}

// ---------------- big parallel GEMM (tf32 wmma) ----------------
#define GT_M 128
#define GT_N 128
#define KCHUNK 16
#define SPAD 20

__global__ void __launch_bounds__(256) gemm_tf32(int phase)
{
    __shared__ float As[GT_M * SPAD];
    __shared__ float Bs[GT_N * SPAD];

    const float* A  = phase ? g_h0s   : g_xcat;
    const float* Bm = phase ? g_Wih1p : g_Wih0p;
    const int K     = phase ? HID     : KIN;

    int tn = blockIdx.x;
    int tm = blockIdx.y;
    int tid = threadIdx.x;
    int wid = tid >> 5;
    int wm = wid >> 2, wn = wid & 3;

    wmma::fragment<wmma::accumulator, 16, 16, 8, float> acc[4][2];
#pragma unroll
    for (int i = 0; i < 4; i++)
#pragma unroll
        for (int j = 0; j < 2; j++) wmma::fill_fragment(acc[i][j], 0.0f);

    const float* Abase = A  + (size_t)tm * GT_M * K;
    const float* Bbase = Bm + (size_t)tn * GT_N * K;

    for (int k0 = 0; k0 < K; k0 += KCHUNK) {
        __syncthreads();
#pragma unroll
        for (int s = tid; s < GT_M * 4; s += 256) {
            int m = s >> 2, q = s & 3;
            *(float4*)&As[m * SPAD + q * 4] = *(const float4*)&Abase[(size_t)m * K + k0 + q * 4];
            *(float4*)&Bs[m * SPAD + q * 4] = *(const float4*)&Bbase[(size_t)m * K + k0 + q * 4];
        }
        __syncthreads();
#pragma unroll
        for (int ks = 0; ks < 2; ks++) {
            wmma::fragment<wmma::matrix_b, 16, 16, 8, wmma::precision::tf32, wmma::col_major> bf[2];
#pragma unroll
            for (int j = 0; j < 2; j++) {
                wmma::load_matrix_sync(bf[j], &Bs[(wn * 32 + j * 16) * SPAD + ks * 8], SPAD);
#pragma unroll
                for (int e = 0; e < bf[j].num_elements; e++)
                    bf[j].x[e] = wmma::__float_to_tf32(bf[j].x[e]);
            }
#pragma unroll
            for (int i = 0; i < 4; i++) {
                wmma::fragment<wmma::matrix_a, 16, 16, 8, wmma::precision::tf32, wmma::row_major> af;
                wmma::load_matrix_sync(af, &As[(wm * 64 + i * 16) * SPAD + ks * 8], SPAD);
#pragma unroll
                for (int e = 0; e < af.num_elements; e++)
                    af.x[e] = wmma::__float_to_tf32(af.x[e]);
#pragma unroll
                for (int j = 0; j < 2; j++) wmma::mma_sync(acc[i][j], af, bf[j], acc[i][j]);
            }
        }
    }
#pragma unroll
    for (int i = 0; i < 4; i++)
#pragma unroll
        for (int j = 0; j < 2; j++) {
            int gm = tm * GT_M + wm * 64 + i * 16;
            int gn = tn * GT_N + wn * 32 + j * 16;
            wmma::store_matrix_sync(&g_xproj[(size_t)gm * GATES + gn], acc[i][j], GATES,
                                    wmma::mem_row_major);
        }
}

// ---------------- persistent recurrent scan (one layer) ----------------
// 64 CTAs x 256 threads. CTA c owns gate cols [32c, 32c+32).
// Per step: stage h(t-1) (64x512) into SMEM via __ldcg float4, then
// 8 warps = 2(m-half 32 rows) x 4(k-quarter 128) compute 32x32 tiles with K=128;
// 4 k-partials summed in the elementwise pass. Cell state lives in registers.
__global__ void __launch_bounds__(NT_SCAN) scan_tf32(int layer)
{
    extern __shared__ float smem[];
    float* As = smem;                   // [64][APAD]
    float* Ws = smem + A_FLOATS;        // [CCOLS][WPAD]
    float* sg = smem;                   // aliases As: [4(kq)][64(b)][SGP]

    const int c   = blockIdx.x;
    const int tid = threadIdx.x;
    const int w   = tid >> 5;
    const int mh  = w & 1;              // m half: rows mh*32..
    const int kq  = w >> 1;             // k quarter: cols kq*128..

    const float* Wp = layer ? g_Whh1p : g_Whh0p;

    // stage W slice into smem (once)
    {
        const float* Wg = Wp + (size_t)c * CCOLS * HID;
#pragma unroll 4
        for (int idx = tid; idx < CCOLS * 128; idx += NT_SCAN) {
            int n = idx >> 7, q = idx & 127;
            *(float4*)&Ws[n * WPAD + q * 4] = *(const float4*)&Wg[(size_t)n * HID + q * 4];
        }
    }

    // fixed per-thread elementwise mapping (2 outputs per thread)
    const int b0 = tid >> 3,           ul0 = tid & 7,          gc0 = ul0 * 4;
    const int p1 = tid + NT_SCAN;
    const int b1 = p1 >> 3,            ul1 = p1 & 7,           gc1 = ul1 * 4;
    const float4 bias0 = *(const float4*)(g_biasP[layer] + c * CCOLS + gc0);
    const float4 bias1 = *(const float4*)(g_biasP[layer] + c * CCOLS + gc1);
    const float* xpp0 = g_xproj + (size_t)b0 * SEQ * GATES + c * CCOLS + gc0;
    const float* xpp1 = g_xproj + (size_t)b1 * SEQ * GATES + c * CCOLS + gc1;
    const int u0 = c * 8 + ul0, u1 = c * 8 + ul1;
    float cst0 = 0.0f, cst1 = 0.0f;    // cell state in registers

    // zero initial h
    for (int i = blockIdx.x * NT_SCAN + tid; i < BATCH * HID; i += NB_SCAN * NT_SCAN)
        g_hbuf[0][i] = 0.0f;

    // barrier epoch base (persists across launches; stream order makes it stable here)
    __shared__ unsigned s_base;
    if (tid == 0) s_base = ld_acquire_gpu(&g_epoch);
    __syncthreads();
    unsigned round = s_base;

    grid_barrier_round(++round);   // h-zero visible everywhere

    for (int t = 0; t < SEQ; t++) {
        // prefetch this step's xproj early (DRAM latency hides under mma)
        float4 xp0 = __ldcs((const float4*)(xpp0 + (size_t)t * GATES));
        float4 xp1 = __ldcs((const float4*)(xpp1 + (size_t)t * GATES));

        const float* hread  = g_hbuf[t & 1];
        float*       hwrite = g_hbuf[(t & 1) ^ 1];

        // stage h(t-1): 8192 float4, L2-only (fresh cross-CTA data)
#pragma unroll 8
        for (int idx = tid; idx < 8192; idx += NT_SCAN) {
            int r = idx >> 7, q = idx & 127;
            float4 v = ldcg4(hread + r * HID + q * 4);
            *(float4*)&As[r * APAD + q * 4] = v;
        }
        __syncthreads();

        // mma: warp tile 32(m) x 32(n), K=128
        wmma::fragment<wmma::accumulator, 16, 16, 8, float> acc[2][2];
#pragma unroll
        for (int i = 0; i < 2; i++)
#pragma unroll
            for (int j = 0; j < 2; j++) wmma::fill_fragment(acc[i][j], 0.0f);

        const float* Abase = &As[mh * 32 * APAD + kq * 128];
        const float* Bbase = &Ws[kq * 128];

#pragma unroll
        for (int ks = 0; ks < 16; ks++) {
            wmma::fragment<wmma::matrix_a, 16, 16, 8, wmma::precision::tf32, wmma::row_major> af[2];
            wmma::fragment<wmma::matrix_b, 16, 16, 8, wmma::precision::tf32, wmma::col_major> bf[2];
#pragma unroll
            for (int i = 0; i < 2; i++) {
                wmma::load_matrix_sync(af[i], Abase + i * 16 * APAD + ks * 8, APAD);
#pragma unroll
                for (int e = 0; e < 4; e++) af[i].x[e] = wmma::__float_to_tf32(af[i].x[e]);
            }
#pragma unroll
            for (int j = 0; j < 2; j++) {
                wmma::load_matrix_sync(bf[j], Bbase + j * 16 * WPAD + ks * 8, WPAD);
#pragma unroll
                for (int e = 0; e < 4; e++) bf[j].x[e] = wmma::__float_to_tf32(bf[j].x[e]);
            }
#pragma unroll
            for (int i = 0; i < 2; i++)
#pragma unroll
                for (int j = 0; j < 2; j++) wmma::mma_sync(acc[i][j], af[i], bf[j], acc[i][j]);
        }

        __syncthreads();   // all warps done reading As before sg (alias) is written

        // store k-partials: sg[kq][64][SGP]
#pragma unroll
        for (int i = 0; i < 2; i++)
#pragma unroll
            for (int j = 0; j < 2; j++)
                wmma::store_matrix_sync(&sg[kq * (64 * SGP) + (mh * 32 + i * 16) * SGP + j * 16],
                                        acc[i][j], SGP, wmma::mem_row_major);
        __syncthreads();

        // elementwise LSTM cell (sum the 4 k-partials here)
        {
            float4 s0 = *(const float4*)&sg[0 * (64 * SGP) + b0 * SGP + gc0];
            float4 s1 = *(const float4*)&sg[1 * (64 * SGP) + b0 * SGP + gc0];
            float4 s2 = *(const float4*)&sg[2 * (64 * SGP) + b0 * SGP + gc0];
            float4 s3 = *(const float4*)&sg[3 * (64 * SGP) + b0 * SGP + gc0];
            float pi = s0.x + s1.x + s2.x + s3.x + xp0.x + bias0.x;
            float pf = s0.y + s1.y + s2.y + s3.y + xp0.y + bias0.y;
            float pg = s0.z + s1.z + s2.z + s3.z + xp0.z + bias0.z;
            float po = s0.w + s1.w + s2.w + s3.w + xp0.w + bias0.w;
            float ig = sigm(pi), fg = sigm(pf), gg = tanhf(pg), og = sigm(po);
            cst0 = fg * cst0 + ig * gg;
            float hv = og * tanhf(cst0);
            hwrite[b0 * HID + u0] = hv;
            if (layer == 0) __stcs(&g_h0s[((size_t)(b0 * SEQ + t)) * HID + u0], hv);
        }
        {
            float4 s0 = *(const float4*)&sg[0 * (64 * SGP) + b1 * SGP + gc1];
            float4 s1 = *(const float4*)&sg[1 * (64 * SGP) + b1 * SGP + gc1];
            float4 s2 = *(const float4*)&sg[2 * (64 * SGP) + b1 * SGP + gc1];
            float4 s3 = *(const float4*)&sg[3 * (64 * SGP) + b1 * SGP + gc1];
            float pi = s0.x + s1.x + s2.x + s3.x + xp1.x + bias1.x;
            float pf = s0.y + s1.y + s2.y + s3.y + xp1.y + bias1.y;
            float pg = s0.z + s1.z + s2.z + s3.z + xp1.z + bias1.z;
            float po = s0.w + s1.w + s2.w + s3.w + xp1.w + bias1.w;
            float ig = sigm(pi), fg = sigm(pf), gg = tanhf(pg), og = sigm(po);
            cst1 = fg * cst1 + ig * gg;
            float hv = og * tanhf(cst1);
            hwrite[b1 * HID + u1] = hv;
            if (layer == 0) __stcs(&g_h0s[((size_t)(b1 * SEQ + t)) * HID + u1], hv);
        }

        grid_barrier_round(++round);
    }
}

// ---------------- output projection ----------------
__global__ void out_kernel(const float* __restrict__ Wout, const float* __restrict__ bout,
                           float* __restrict__ out)
{
    int b = blockIdx.x;
    int o = threadIdx.x;
    const float* h  = g_hbuf[0] + b * HID;   // SEQ even -> final h in buffer 0
    const float* wr = Wout + o * HID;
    float acc = bout[o];
#pragma unroll 8
    for (int u = 0; u < HID; u++) acc = fmaf(h[u], wr[u], acc);
    out[b * ODIM + o] = acc;
}

// ---------------- launch ----------------
extern "C" void kernel_launch(void* const* d_in, const int* in_sizes, int n_in,
                              void* d_out, int out_size)
{
    (void)in_sizes; (void)n_in; (void)out_size;
    const float* prim = (const float*)d_in[0];
    const float* aux  = (const float*)d_in[1];
    const float* Wih0 = (const float*)d_in[2];
    const float* Whh0 = (const float*)d_in[3];
    const float* bih0 = (const float*)d_in[4];
    const float* bhh0 = (const float*)d_in[5];
    const float* Wih1 = (const float*)d_in[6];
    const float* Whh1 = (const float*)d_in[7];
    const float* bih1 = (const float*)d_in[8];
    const float* bhh1 = (const float*)d_in[9];
    const float* Wout = (const float*)d_in[10];
    const float* bout = (const float*)d_in[11];
    float* out = (float*)d_out;

    static bool attr_set = false;
    if (!attr_set) {
        cudaFuncSetAttribute(scan_tf32, cudaFuncAttributeMaxDynamicSharedMemorySize,
                             SCAN_SMEM_BYTES);
        attr_set = true;
    }

    prep_kernel<<<1024, 256>>>(prim, aux, Wih0, Whh0, bih0, bhh0, Wih1, Whh1, bih1, bhh1);
    gemm_tf32<<<dim3(16, 256), 256>>>(0);                        // x_proj0
    scan_tf32<<<NB_SCAN, NT_SCAN, SCAN_SMEM_BYTES>>>(0);         // layer-0 scan
    gemm_tf32<<<dim3(16, 256), 256>>>(1);                        // x_proj1
    scan_tf32<<<NB_SCAN, NT_SCAN, SCAN_SMEM_BYTES>>>(1);         // layer-1 scan
    out_kernel<<<BATCH, ODIM>>>(Wout, bout, out);
}

// round 5
// speedup vs baseline: 2.9281x; 1.0505x over previous
#include <cuda_runtime.h>
#include <cuda_bf16.h>
#include <mma.h>

using namespace nvcuda;

#define BATCH 64
#define SEQ   512
#define HID   512
#define GATES 2048      // 4*HID
#define KIN   96        // 64 + 32
#define ODIM  128

#define NB_SCAN 64
#define NT_SCAN 256
#define CCOLS   32      // gate cols per CTA
#define APAD    516     // stride mod 32 = 4 -> conflict-light, %4==0 for float4
#define SGP     36      // sg row pad
#define A_FLOATS (64 * APAD)
#define W_FLOATS (CCOLS * APAD)
#define SCAN_SMEM_BYTES ((A_FLOATS + W_FLOATS) * 4)   // 198,144 B

// ---------------- static device scratch ----------------
__device__ float g_xproj[(size_t)BATCH * SEQ * GATES];
__device__ float g_h0s[(size_t)BATCH * SEQ * HID];
__device__ float g_xcat[(size_t)BATCH * SEQ * KIN];
__device__ float g_Wih0p[GATES * KIN];
__device__ float g_Whh0p[GATES * HID];
__device__ float g_Wih1p[GATES * HID];
__device__ float g_Whh1p[GATES * HID];
__device__ float g_biasP[2][GATES];
__device__ float g_hbuf[2][BATCH * HID];
__device__ unsigned g_arrive;   // monotonic arrival counter
__device__ unsigned g_epoch;    // monotonic completed-round counter

// ---------------- release/acquire primitives ----------------
__device__ __forceinline__ unsigned ld_acquire_gpu(unsigned* p) {
    unsigned v;
    asm volatile("ld.acquire.gpu.global.u32 %0, [%1];" : "=r"(v) : "l"(p) : "memory");
    return v;
}
__device__ __forceinline__ unsigned atom_add_release_gpu(unsigned* p, unsigned v) {
    unsigned old;
    asm volatile("atom.release.gpu.global.add.u32 %0, [%1], %2;"
                 : "=r"(old) : "l"(p), "r"(v) : "memory");
    return old;
}
__device__ __forceinline__ void st_release_gpu(unsigned* p, unsigned v) {
    asm volatile("st.release.gpu.global.u32 [%0], %1;" :: "l"(p), "r"(v) : "memory");
}

// monotonic-epoch grid barrier. round is absolute (continues across launches/replays).
__device__ __forceinline__ void grid_barrier_round(unsigned round) {
    __syncthreads();
    if (threadIdx.x == 0) {
        unsigned prev = atom_add_release_gpu(&g_arrive, 1u);
        if (prev + 1u == round * NB_SCAN) {
            st_release_gpu(&g_epoch, round);
        } else {
            while ((int)(ld_acquire_gpu(&g_epoch) - round) < 0) { }
        }
    }
    __syncthreads();
}

__device__ __forceinline__ float sigm(float x) { return 1.0f / (1.0f + expf(-x)); }

// ---------------- prep: concat input, permute weights (col' = 4u+gate) ----------------
__global__ void prep_kernel(const float* __restrict__ prim, const float* __restrict__ aux,
                            const float* __restrict__ Wih0, const float* __restrict__ Whh0,
                            const float* __restrict__ bih0, const float* __restrict__ bhh0,
                            const float* __restrict__ Wih1, const float* __restrict__ Whh1,
                            const float* __restrict__ bih1, const float* __restrict__ bhh1)
{
    size_t tid = (size_t)blockIdx.x * blockDim.x + threadIdx.x;
    size_t nth = (size_t)gridDim.x * blockDim.x;

    for (size_t i = tid; i < (size_t)BATCH * SEQ * KIN; i += nth) {
        int k = (int)(i % KIN);
        size_t bt = i / KIN;
        int b = (int)(bt / SEQ);
        g_xcat[i] = (k < 64) ? prim[bt * 64 + k] : aux[b * 32 + (k - 64)];
    }
    for (size_t i = tid; i < (size_t)GATES * HID; i += nth) {
        int k  = (int)(i % HID);
        int cp = (int)(i / HID);
        int u = cp >> 2, gi = cp & 3;
        size_t r = (size_t)(gi * HID + u) * HID + k;
        g_Whh0p[i] = Whh0[r];
        g_Whh1p[i] = Whh1[r];
        g_Wih1p[i] = Wih1[r];
    }
    for (size_t i = tid; i < (size_t)GATES * KIN; i += nth) {
        int k  = (int)(i % KIN);
        int cp = (int)(i / KIN);
        int u = cp >> 2, gi = cp & 3;
        g_Wih0p[i] = Wih0[(size_t)(gi * HID + u) * KIN + k];
    }
    for (size_t i = tid; i < GATES; i += nth) {
        int u = (int)(i >> 2), gi = (int)(i & 3);
        int r = gi * HID + u;
        g_biasP[0][i] = bih0[r] + bhh0[r];
        g_biasP[1][i] = bih1[r] + bhh1[r];
    }
}

// ---------------- big parallel GEMM (tf32 wmma, no explicit cvt) ----------------
#define GT_M 128
#define GT_N 128
#define KCHUNK 16
#define SPAD 20

__global__ void __launch_bounds__(256) gemm_tf32(int phase)
{
    __shared__ float As[GT_M * SPAD];
    __shared__ float Bs[GT_N * SPAD];

    const float* A  = phase ? g_h0s   : g_xcat;
    const float* Bm = phase ? g_Wih1p : g_Wih0p;
    const int K     = phase ? HID     : KIN;

    int tn = blockIdx.x;
    int tm = blockIdx.y;
    int tid = threadIdx.x;
    int wid = tid >> 5;
    int wm = wid >> 2, wn = wid & 3;

    wmma::fragment<wmma::accumulator, 16, 16, 8, float> acc[4][2];
#pragma unroll
    for (int i = 0; i < 4; i++)
#pragma unroll
        for (int j = 0; j < 2; j++) wmma::fill_fragment(acc[i][j], 0.0f);

    const float* Abase = A  + (size_t)tm * GT_M * K;
    const float* Bbase = Bm + (size_t)tn * GT_N * K;

    for (int k0 = 0; k0 < K; k0 += KCHUNK) {
        __syncthreads();
#pragma unroll
        for (int s = tid; s < GT_M * 4; s += 256) {
            int m = s >> 2, q = s & 3;
            *(float4*)&As[m * SPAD + q * 4] = *(const float4*)&Abase[(size_t)m * K + k0 + q * 4];
            *(float4*)&Bs[m * SPAD + q * 4] = *(const float4*)&Bbase[(size_t)m * K + k0 + q * 4];
        }
        __syncthreads();
#pragma unroll
        for (int ks = 0; ks < 2; ks++) {
            wmma::fragment<wmma::matrix_b, 16, 16, 8, wmma::precision::tf32, wmma::col_major> bf[2];
#pragma unroll
            for (int j = 0; j < 2; j++)
                wmma::load_matrix_sync(bf[j], &Bs[(wn * 32 + j * 16) * SPAD + ks * 8], SPAD);
#pragma unroll
            for (int i = 0; i < 4; i++) {
                wmma::fragment<wmma::matrix_a, 16, 16, 8, wmma::precision::tf32, wmma::row_major> af;
                wmma::load_matrix_sync(af, &As[(wm * 64 + i * 16) * SPAD + ks * 8], SPAD);
#pragma unroll
                for (int j = 0; j < 2; j++) wmma::mma_sync(acc[i][j], af, bf[j], acc[i][j]);
            }
        }
    }
#pragma unroll
    for (int i = 0; i < 4; i++)
#pragma unroll
        for (int j = 0; j < 2; j++) {
            int gm = tm * GT_M + wm * 64 + i * 16;
            int gn = tn * GT_N + wn * 32 + j * 16;
            wmma::store_matrix_sync(&g_xproj[(size_t)gm * GATES + gn], acc[i][j], GATES,
                                    wmma::mem_row_major);
        }
}

// ---------------- persistent recurrent scan (one layer) ----------------
// 64 CTAs x 256 threads. CTA c owns gate cols [32c, 32c+32).
// Warp (mh,kq) stages ONLY its own A tile (rows mh*32..+32, k cols kq*128..+128),
// __syncwarp, then mma — no full-CTA sync before compute. No tf32 cvt (HW truncates).
__global__ void __launch_bounds__(NT_SCAN) scan_tf32(int layer)
{
    extern __shared__ float smem[];
    float* As = smem;                   // [64][APAD]
    float* Ws = smem + A_FLOATS;        // [CCOLS][APAD]
    float* sg = smem;                   // aliases As head: [4(kq)][64(b)][SGP]

    const int c    = blockIdx.x;
    const int tid  = threadIdx.x;
    const int w    = tid >> 5;
    const int lane = tid & 31;
    const int mh   = w & 1;             // m half
    const int kq   = w >> 1;            // k quarter

    const float* Wp = layer ? g_Whh1p : g_Whh0p;

    // stage W slice into smem (once)
    {
        const float* Wg = Wp + (size_t)c * CCOLS * HID;
#pragma unroll 4
        for (int idx = tid; idx < CCOLS * 128; idx += NT_SCAN) {
            int n = idx >> 7, q = idx & 127;
            *(float4*)&Ws[n * APAD + q * 4] = *(const float4*)&Wg[(size_t)n * HID + q * 4];
        }
    }

    // fixed per-thread elementwise mapping (2 outputs per thread)
    const int b0 = tid >> 3,  ul0 = tid & 7,  gc0 = ul0 * 4;
    const int p1 = tid + NT_SCAN;
    const int b1 = p1 >> 3,   ul1 = p1 & 7,   gc1 = ul1 * 4;
    const float4 bias0 = *(const float4*)(g_biasP[layer] + c * CCOLS + gc0);
    const float4 bias1 = *(const float4*)(g_biasP[layer] + c * CCOLS + gc1);
    const float* xpp0 = g_xproj + (size_t)b0 * SEQ * GATES + c * CCOLS + gc0;
    const float* xpp1 = g_xproj + (size_t)b1 * SEQ * GATES + c * CCOLS + gc1;
    const int u0 = c * 8 + ul0, u1 = c * 8 + ul1;
    float cst0 = 0.0f, cst1 = 0.0f;    // cell state in registers

    // zero initial h
    for (int i = blockIdx.x * NT_SCAN + tid; i < BATCH * HID; i += NB_SCAN * NT_SCAN)
        g_hbuf[0][i] = 0.0f;

    // barrier epoch base (persists across launches; stream order makes it stable)
    __shared__ unsigned s_base;
    if (tid == 0) s_base = ld_acquire_gpu(&g_epoch);
    __syncthreads();
    unsigned round = s_base;

    grid_barrier_round(++round);   // h-zero visible everywhere

    // prefetch step-0 xproj
    float4 xp0 = __ldcs((const float4*)xpp0);
    float4 xp1 = __ldcs((const float4*)xpp1);

    for (int t = 0; t < SEQ; t++) {
        const float* hread  = g_hbuf[t & 1];
        float*       hwrite = g_hbuf[(t & 1) ^ 1];

        // warp-local stage of this warp's A tile: rows mh*32..+32, cols kq*128..+128.
        // pass i: one full row (32 float4 across the warp, 512B contiguous)
        {
            const float* src = hread + (size_t)(mh * 32) * HID + kq * 128 + lane * 4;
            float* dst = &As[(mh * 32) * APAD + kq * 128 + lane * 4];
#pragma unroll
            for (int i = 0; i < 32; i++) {
                float4 v = __ldcg((const float4*)(src + (size_t)i * HID));
                *(float4*)(dst + i * APAD) = v;
            }
        }
        __syncwarp();

        // mma: warp tile 32(m) x 32(n), K=128 — pure LDS + HMMA
        wmma::fragment<wmma::accumulator, 16, 16, 8, float> acc[2][2];
#pragma unroll
        for (int i = 0; i < 2; i++)
#pragma unroll
            for (int j = 0; j < 2; j++) wmma::fill_fragment(acc[i][j], 0.0f);

        const float* Abase = &As[mh * 32 * APAD + kq * 128];
        const float* Bbase = &Ws[kq * 128];

#pragma unroll
        for (int ks = 0; ks < 16; ks++) {
            wmma::fragment<wmma::matrix_a, 16, 16, 8, wmma::precision::tf32, wmma::row_major> af[2];
            wmma::fragment<wmma::matrix_b, 16, 16, 8, wmma::precision::tf32, wmma::col_major> bf[2];
#pragma unroll
            for (int i = 0; i < 2; i++)
                wmma::load_matrix_sync(af[i], Abase + i * 16 * APAD + ks * 8, APAD);
#pragma unroll
            for (int j = 0; j < 2; j++)
                wmma::load_matrix_sync(bf[j], Bbase + j * 16 * APAD + ks * 8, APAD);
#pragma unroll
            for (int i = 0; i < 2; i++)
#pragma unroll
                for (int j = 0; j < 2; j++) wmma::mma_sync(acc[i][j], af[i], bf[j], acc[i][j]);
        }

        __syncthreads();   // all warps done reading As before sg (alias) is written

        // store k-partials: sg[kq][64][SGP]
#pragma unroll
        for (int i = 0; i < 2; i++)
#pragma unroll
            for (int j = 0; j < 2; j++)
                wmma::store_matrix_sync(&sg[kq * (64 * SGP) + (mh * 32 + i * 16) * SGP + j * 16],
                                        acc[i][j], SGP, wmma::mem_row_major);
        __syncthreads();

        // elementwise LSTM cell (sum the 4 k-partials here)
        {
            float4 s0 = *(const float4*)&sg[0 * (64 * SGP) + b0 * SGP + gc0];
            float4 s1 = *(const float4*)&sg[1 * (64 * SGP) + b0 * SGP + gc0];
            float4 s2 = *(const float4*)&sg[2 * (64 * SGP) + b0 * SGP + gc0];
            float4 s3 = *(const float4*)&sg[3 * (64 * SGP) + b0 * SGP + gc0];
            float pi = s0.x + s1.x + s2.x + s3.x + xp0.x + bias0.x;
            float pf = s0.y + s1.y + s2.y + s3.y + xp0.y + bias0.y;
            float pg = s0.z + s1.z + s2.z + s3.z + xp0.z + bias0.z;
            float po = s0.w + s1.w + s2.w + s3.w + xp0.w + bias0.w;
            float ig = sigm(pi), fg = sigm(pf), gg = tanhf(pg), og = sigm(po);
            cst0 = fg * cst0 + ig * gg;
            float hv = og * tanhf(cst0);
            hwrite[b0 * HID + u0] = hv;
            if (layer == 0) __stcs(&g_h0s[((size_t)(b0 * SEQ + t)) * HID + u0], hv);
        }
        {
            float4 s0 = *(const float4*)&sg[0 * (64 * SGP) + b1 * SGP + gc1];
            float4 s1 = *(const float4*)&sg[1 * (64 * SGP) + b1 * SGP + gc1];
            float4 s2 = *(const float4*)&sg[2 * (64 * SGP) + b1 * SGP + gc1];
            float4 s3 = *(const float4*)&sg[3 * (64 * SGP) + b1 * SGP + gc1];
            float pi = s0.x + s1.x + s2.x + s3.x + xp1.x + bias1.x;
            float pf = s0.y + s1.y + s2.y + s3.y + xp1.y + bias1.y;
            float pg = s0.z + s1.z + s2.z + s3.z + xp1.z + bias1.z;
            float po = s0.w + s1.w + s2.w + s3.w + xp1.w + bias1.w;
            float ig = sigm(pi), fg = sigm(pf), gg = tanhf(pg), og = sigm(po);
            cst1 = fg * cst1 + ig * gg;
            float hv = og * tanhf(cst1);
            hwrite[b1 * HID + u1] = hv;
            if (layer == 0) __stcs(&g_h0s[((size_t)(b1 * SEQ + t)) * HID + u1], hv);
        }

        // prefetch next step's xproj BEFORE the barrier (in flight during the wait)
        {
            int tn = (t + 1 < SEQ) ? (t + 1) : (SEQ - 1);
            xp0 = __ldcs((const float4*)(xpp0 + (size_t)tn * GATES));
            xp1 = __ldcs((const float4*)(xpp1 + (size_t)tn * GATES));
        }

        grid_barrier_round(++round);
    }
}

// ---------------- output projection ----------------
__global__ void out_kernel(const float* __restrict__ Wout, const float* __restrict__ bout,
                           float* __restrict__ out)
{
    int b = blockIdx.x;
    int o = threadIdx.x;
    const float* h  = g_hbuf[0] + b * HID;   // SEQ even -> final h in buffer 0
    const float* wr = Wout + o * HID;
    float acc = bout[o];
#pragma unroll 8
    for (int u = 0; u < HID; u++) acc = fmaf(h[u], wr[u], acc);
    out[b * ODIM + o] = acc;
}

// ---------------- launch ----------------
extern "C" void kernel_launch(void* const* d_in, const int* in_sizes, int n_in,
                              void* d_out, int out_size)
{
    (void)in_sizes; (void)n_in; (void)out_size;
    const float* prim = (const float*)d_in[0];
    const float* aux  = (const float*)d_in[1];
    const float* Wih0 = (const float*)d_in[2];
    const float* Whh0 = (const float*)d_in[3];
    const float* bih0 = (const float*)d_in[4];
    const float* bhh0 = (const float*)d_in[5];
    const float* Wih1 = (const float*)d_in[6];
    const float* Whh1 = (const float*)d_in[7];
    const float* bih1 = (const float*)d_in[8];
    const float* bhh1 = (const float*)d_in[9];
    const float* Wout = (const float*)d_in[10];
    const float* bout = (const float*)d_in[11];
    float* out = (float*)d_out;

    static bool attr_set = false;
    if (!attr_set) {
        cudaFuncSetAttribute(scan_tf32, cudaFuncAttributeMaxDynamicSharedMemorySize,
                             SCAN_SMEM_BYTES);
        attr_set = true;
    }

    prep_kernel<<<1024, 256>>>(prim, aux, Wih0, Whh0, bih0, bhh0, Wih1, Whh1, bih1, bhh1);
    gemm_tf32<<<dim3(16, 256), 256>>>(0);                        // x_proj0
    scan_tf32<<<NB_SCAN, NT_SCAN, SCAN_SMEM_BYTES>>>(0);         // layer-0 scan
    gemm_tf32<<<dim3(16, 256), 256>>>(1);                        // x_proj1
    scan_tf32<<<NB_SCAN, NT_SCAN, SCAN_SMEM_BYTES>>>(1);         // layer-1 scan
    out_kernel<<<BATCH, ODIM>>>(Wout, bout, out);
}

// round 6
// speedup vs baseline: 3.4493x; 1.1780x over previous
#include <cuda_runtime.h>
#include <cuda_bf16.h>
#include <mma.h>

using namespace nvcuda;

#define BATCH 64
#define SEQ   512
#define HID   512
#define GATES 2048      // 4*HID
#define KIN   96        // 64 + 32
#define ODIM  128

#define NB_SCAN 128     // 64 layer-0 CTAs + 64 layer-1 CTAs
#define NT_SCAN 256
#define CCOLS   32      // gate cols per CTA
#define APAD    516
#define W1PAD   1028    // layer-1 concat W row stride (1024 + 4)
#define SGP     36
// layer-0 layout: As[64][APAD] + Ws[32][APAD]
#define L0_A_FLOATS (64 * APAD)
#define L0_TOTAL    ((64 + CCOLS) * APAD)              // 49536 floats
// layer-1 layout: Ws1[32][W1PAD] + As1[32][APAD]
#define L1_W_FLOATS (CCOLS * W1PAD)                    // 32896
#define L1_TOTAL    (L1_W_FLOATS + 32 * APAD)          // 49408 floats
#define SCAN_SMEM_BYTES (L0_TOTAL * 4)                 // 198,144 B (>= L1_TOTAL*4)

// ---------------- static device scratch ----------------
__device__ float g_xproj[(size_t)BATCH * SEQ * GATES];   // layer-0 input projections
__device__ float g_xcat[(size_t)BATCH * SEQ * KIN];
__device__ float g_Wih0p[GATES * KIN];
__device__ float g_Whh0p[GATES * HID];
__device__ float g_Wih1p[GATES * HID];
__device__ float g_Whh1p[GATES * HID];
__device__ float g_biasP[2][GATES];
__device__ float g_hbuf0[2][BATCH * HID];
__device__ float g_hbuf1[2][BATCH * HID];
__device__ unsigned g_arrive;   // monotonic arrival counter
__device__ unsigned g_epoch;    // monotonic completed-round counter

// ---------------- release/acquire primitives ----------------
__device__ __forceinline__ unsigned ld_acquire_gpu(unsigned* p) {
    unsigned v;
    asm volatile("ld.acquire.gpu.global.u32 %0, [%1];" : "=r"(v) : "l"(p) : "memory");
    return v;
}
__device__ __forceinline__ unsigned atom_add_release_gpu(unsigned* p, unsigned v) {
    unsigned old;
    asm volatile("atom.release.gpu.global.add.u32 %0, [%1], %2;"
                 : "=r"(old) : "l"(p), "r"(v) : "memory");
    return old;
}
__device__ __forceinline__ void st_release_gpu(unsigned* p, unsigned v) {
    asm volatile("st.release.gpu.global.u32 [%0], %1;" :: "l"(p), "r"(v) : "memory");
}

// monotonic-epoch grid barrier (round is absolute across launches/replays)
__device__ __forceinline__ void grid_barrier_round(unsigned round) {
    __syncthreads();
    if (threadIdx.x == 0) {
        unsigned prev = atom_add_release_gpu(&g_arrive, 1u);
        if (prev + 1u == round * NB_SCAN) {
            st_release_gpu(&g_epoch, round);
        } else {
            while ((int)(ld_acquire_gpu(&g_epoch) - round) < 0) { }
        }
    }
    __syncthreads();
}

__device__ __forceinline__ float sigm(float x) { return 1.0f / (1.0f + expf(-x)); }

__device__ __forceinline__ float tf32_rna(float x) {
    unsigned u;
    asm("cvt.rna.tf32.f32 %0, %1;" : "=r"(u) : "f"(x));
    return __uint_as_float(u);
}

// ---------------- prep: concat input, permute + tf32-round weights ----------------
// col' = 4*u + gate  <->  original row r = gate*HID + u
__global__ void prep_kernel(const float* __restrict__ prim, const float* __restrict__ aux,
                            const float* __restrict__ Wih0, const float* __restrict__ Whh0,
                            const float* __restrict__ bih0, const float* __restrict__ bhh0,
                            const float* __restrict__ Wih1, const float* __restrict__ Whh1,
                            const float* __restrict__ bih1, const float* __restrict__ bhh1)
{
    size_t tid = (size_t)blockIdx.x * blockDim.x + threadIdx.x;
    size_t nth = (size_t)gridDim.x * blockDim.x;

    for (size_t i = tid; i < (size_t)BATCH * SEQ * KIN; i += nth) {
        int k = (int)(i % KIN);
        size_t bt = i / KIN;
        int b = (int)(bt / SEQ);
        g_xcat[i] = tf32_rna((k < 64) ? prim[bt * 64 + k] : aux[b * 32 + (k - 64)]);
    }
    for (size_t i = tid; i < (size_t)GATES * HID; i += nth) {
        int k  = (int)(i % HID);
        int cp = (int)(i / HID);
        int u = cp >> 2, gi = cp & 3;
        size_t r = (size_t)(gi * HID + u) * HID + k;
        g_Whh0p[i] = tf32_rna(Whh0[r]);
        g_Whh1p[i] = tf32_rna(Whh1[r]);
        g_Wih1p[i] = tf32_rna(Wih1[r]);
    }
    for (size_t i = tid; i < (size_t)GATES * KIN; i += nth) {
        int k  = (int)(i % KIN);
        int cp = (int)(i / KIN);
        int u = cp >> 2, gi = cp & 3;
        g_Wih0p[i] = tf32_rna(Wih0[(size_t)(gi * HID + u) * KIN + k]);
    }
    for (size_t i = tid; i < GATES; i += nth) {
        int u = (int)(i >> 2), gi = (int)(i & 3);
        int r = gi * HID + u;
        g_biasP[0][i] = bih0[r] + bhh0[r];
        g_biasP[1][i] = bih1[r] + bhh1[r];
    }
}

// ---------------- x_proj0 GEMM (tf32 wmma): C[32768 x 2048] = xcat @ Wih0p^T ----------------
#define GT_M 128
#define GT_N 128
#define KCHUNK 16
#define SPAD 20

__global__ void __launch_bounds__(256) gemm_tf32()
{
    __shared__ float As[GT_M * SPAD];
    __shared__ float Bs[GT_N * SPAD];

    const float* A  = g_xcat;
    const float* Bm = g_Wih0p;
    const int K     = KIN;

    int tn = blockIdx.x;
    int tm = blockIdx.y;
    int tid = threadIdx.x;
    int wid = tid >> 5;
    int wm = wid >> 2, wn = wid & 3;

    wmma::fragment<wmma::accumulator, 16, 16, 8, float> acc[4][2];
#pragma unroll
    for (int i = 0; i < 4; i++)
#pragma unroll
        for (int j = 0; j < 2; j++) wmma::fill_fragment(acc[i][j], 0.0f);

    const float* Abase = A  + (size_t)tm * GT_M * K;
    const float* Bbase = Bm + (size_t)tn * GT_N * K;

    for (int k0 = 0; k0 < K; k0 += KCHUNK) {
        __syncthreads();
#pragma unroll
        for (int s = tid; s < GT_M * 4; s += 256) {
            int m = s >> 2, q = s & 3;
            *(float4*)&As[m * SPAD + q * 4] = *(const float4*)&Abase[(size_t)m * K + k0 + q * 4];
            *(float4*)&Bs[m * SPAD + q * 4] = *(const float4*)&Bbase[(size_t)m * K + k0 + q * 4];
        }
        __syncthreads();
#pragma unroll
        for (int ks = 0; ks < 2; ks++) {
            wmma::fragment<wmma::matrix_b, 16, 16, 8, wmma::precision::tf32, wmma::col_major> bf[2];
#pragma unroll
            for (int j = 0; j < 2; j++)
                wmma::load_matrix_sync(bf[j], &Bs[(wn * 32 + j * 16) * SPAD + ks * 8], SPAD);
#pragma unroll
            for (int i = 0; i < 4; i++) {
                wmma::fragment<wmma::matrix_a, 16, 16, 8, wmma::precision::tf32, wmma::row_major> af;
                wmma::load_matrix_sync(af, &As[(wm * 64 + i * 16) * SPAD + ks * 8], SPAD);
#pragma unroll
                for (int j = 0; j < 2; j++) wmma::mma_sync(acc[i][j], af, bf[j], acc[i][j]);
            }
        }
    }
#pragma unroll
    for (int i = 0; i < 4; i++)
#pragma unroll
        for (int j = 0; j < 2; j++) {
            int gm = tm * GT_M + wm * 64 + i * 16;
            int gn = tn * GT_N + wn * 32 + j * 16;
            wmma::store_matrix_sync(&g_xproj[(size_t)gm * GATES + gn], acc[i][j], GATES,
                                    wmma::mem_row_major);
        }
}

// ---------------- fused dual-layer persistent scan ----------------
// 128 CTAs x 256 threads. CTAs [0,64): layer 0; [64,128): layer 1 (lag 1).
// Round r: L0 computes h0[r] (r<512); L1 computes h1[r-1] (r>=1). 513 rounds.
__global__ void __launch_bounds__(NT_SCAN) scan_fused()
{
    extern __shared__ float smem[];

    const int tid  = threadIdx.x;
    const int w    = tid >> 5;
    const int lane = tid & 31;
    const int grp  = blockIdx.x >> 6;          // 0 = layer0, 1 = layer1
    const int c    = blockIdx.x & 63;          // gate-col block: cols [32c, 32c+32)

    // zero initial states
    for (int i = blockIdx.x * NT_SCAN + tid; i < BATCH * HID; i += NB_SCAN * NT_SCAN) {
        g_hbuf0[0][i] = 0.0f;
        g_hbuf1[0][i] = 0.0f;
    }

    __shared__ unsigned s_base;
    if (tid == 0) s_base = ld_acquire_gpu(&g_epoch);
    __syncthreads();
    unsigned round = s_base;

    if (grp == 0) {
        // ---------------- layer 0 ----------------
        float* As = smem;                       // [64][APAD]
        float* Ws = smem + L0_A_FLOATS;         // [32][APAD]
        float* sg = smem;                       // alias: [4][64][SGP]

        const int mh = w & 1;                   // m half (32 rows)
        const int kq = w >> 1;                  // k quarter (128 cols)

        {   // stage W slice once
            const float* Wg = g_Whh0p + (size_t)c * CCOLS * HID;
#pragma unroll 4
            for (int idx = tid; idx < CCOLS * 128; idx += NT_SCAN) {
                int n = idx >> 7, q = idx & 127;
                *(float4*)&Ws[n * APAD + q * 4] = *(const float4*)&Wg[(size_t)n * HID + q * 4];
            }
        }

        const int b0 = tid >> 3,  ul0 = tid & 7,  gc0 = ul0 * 4;
        const int p1 = tid + NT_SCAN;
        const int b1 = p1 >> 3,   ul1 = p1 & 7,   gc1 = ul1 * 4;
        const float4 bias0 = *(const float4*)(g_biasP[0] + c * CCOLS + gc0);
        const float4 bias1 = *(const float4*)(g_biasP[0] + c * CCOLS + gc1);
        const float* xpp0 = g_xproj + (size_t)b0 * SEQ * GATES + c * CCOLS + gc0;
        const float* xpp1 = g_xproj + (size_t)b1 * SEQ * GATES + c * CCOLS + gc1;
        const int u0 = c * 8 + ul0, u1 = c * 8 + ul1;
        float cst0 = 0.0f, cst1 = 0.0f;

        grid_barrier_round(++round);            // zero-init visible

        float4 xp0 = __ldcs((const float4*)xpp0);
        float4 xp1 = __ldcs((const float4*)xpp1);

        for (int r = 0; r < SEQ + 1; r++) {
            if (r < SEQ) {
                const int t = r;
                const float* hread  = g_hbuf0[t & 1];
                float*       hwrite = g_hbuf0[(t & 1) ^ 1];

                // warp-local A staging
                {
                    const float* src = hread + (size_t)(mh * 32) * HID + kq * 128 + lane * 4;
                    float* dst = &As[(mh * 32) * APAD + kq * 128 + lane * 4];
#pragma unroll
                    for (int i = 0; i < 32; i++)
                        *(float4*)(dst + i * APAD) = __ldcg((const float4*)(src + (size_t)i * HID));
                }
                __syncwarp();

                wmma::fragment<wmma::accumulator, 16, 16, 8, float> acc[2][2];
#pragma unroll
                for (int i = 0; i < 2; i++)
#pragma unroll
                    for (int j = 0; j < 2; j++) wmma::fill_fragment(acc[i][j], 0.0f);

                const float* Abase = &As[mh * 32 * APAD + kq * 128];
                const float* Bbase = &Ws[kq * 128];
#pragma unroll
                for (int ks = 0; ks < 16; ks++) {
                    wmma::fragment<wmma::matrix_a, 16, 16, 8, wmma::precision::tf32, wmma::row_major> af[2];
                    wmma::fragment<wmma::matrix_b, 16, 16, 8, wmma::precision::tf32, wmma::col_major> bf[2];
#pragma unroll
                    for (int i = 0; i < 2; i++)
                        wmma::load_matrix_sync(af[i], Abase + i * 16 * APAD + ks * 8, APAD);
#pragma unroll
                    for (int j = 0; j < 2; j++)
                        wmma::load_matrix_sync(bf[j], Bbase + j * 16 * APAD + ks * 8, APAD);
#pragma unroll
                    for (int i = 0; i < 2; i++)
#pragma unroll
                        for (int j = 0; j < 2; j++) wmma::mma_sync(acc[i][j], af[i], bf[j], acc[i][j]);
                }
                __syncthreads();
#pragma unroll
                for (int i = 0; i < 2; i++)
#pragma unroll
                    for (int j = 0; j < 2; j++)
                        wmma::store_matrix_sync(&sg[kq * (64 * SGP) + (mh * 32 + i * 16) * SGP + j * 16],
                                                acc[i][j], SGP, wmma::mem_row_major);
                __syncthreads();

                {
                    float4 s0 = *(const float4*)&sg[0 * (64 * SGP) + b0 * SGP + gc0];
                    float4 s1 = *(const float4*)&sg[1 * (64 * SGP) + b0 * SGP + gc0];
                    float4 s2 = *(const float4*)&sg[2 * (64 * SGP) + b0 * SGP + gc0];
                    float4 s3 = *(const float4*)&sg[3 * (64 * SGP) + b0 * SGP + gc0];
                    float pi = s0.x + s1.x + s2.x + s3.x + xp0.x + bias0.x;
                    float pf = s0.y + s1.y + s2.y + s3.y + xp0.y + bias0.y;
                    float pg = s0.z + s1.z + s2.z + s3.z + xp0.z + bias0.z;
                    float po = s0.w + s1.w + s2.w + s3.w + xp0.w + bias0.w;
                    float ig = sigm(pi), fg = sigm(pf), gg = tanhf(pg), og = sigm(po);
                    cst0 = fg * cst0 + ig * gg;
                    hwrite[b0 * HID + u0] = og * tanhf(cst0);
                }
                {
                    float4 s0 = *(const float4*)&sg[0 * (64 * SGP) + b1 * SGP + gc1];
                    float4 s1 = *(const float4*)&sg[1 * (64 * SGP) + b1 * SGP + gc1];
                    float4 s2 = *(const float4*)&sg[2 * (64 * SGP) + b1 * SGP + gc1];
                    float4 s3 = *(const float4*)&sg[3 * (64 * SGP) + b1 * SGP + gc1];
                    float pi = s0.x + s1.x + s2.x + s3.x + xp1.x + bias1.x;
                    float pf = s0.y + s1.y + s2.y + s3.y + xp1.y + bias1.y;
                    float pg = s0.z + s1.z + s2.z + s3.z + xp1.z + bias1.z;
                    float po = s0.w + s1.w + s2.w + s3.w + xp1.w + bias1.w;
                    float ig = sigm(pi), fg = sigm(pf), gg = tanhf(pg), og = sigm(po);
                    cst1 = fg * cst1 + ig * gg;
                    hwrite[b1 * HID + u1] = og * tanhf(cst1);
                }
                // prefetch next xproj before the barrier
                int tn = (t + 1 < SEQ) ? (t + 1) : (SEQ - 1);
                xp0 = __ldcs((const float4*)(xpp0 + (size_t)tn * GATES));
                xp1 = __ldcs((const float4*)(xpp1 + (size_t)tn * GATES));
            }
            grid_barrier_round(++round);
        }
    } else {
        // ---------------- layer 1 (lag 1) ----------------
        float* Ws1 = smem;                      // [32][W1PAD]  (cols 0-511: Wih1, 512-1023: Whh1)
        float* As1 = smem + L1_W_FLOATS;        // [32][APAD]
        float* sg  = As1;                       // alias: [4][32][SGP]

        const int mhw = w & 1;                  // 16-row half within the 32-row block
        const int kq  = w >> 1;                 // 128-col k quarter within a 512 pass

        {   // stage concat W once: 32 rows x 1024
            const float* Wx = g_Wih1p + (size_t)c * CCOLS * HID;
            const float* Wh = g_Whh1p + (size_t)c * CCOLS * HID;
#pragma unroll 4
            for (int idx = tid; idx < CCOLS * 256; idx += NT_SCAN) {
                int n = idx >> 8, q = idx & 255;
                const float* src = (q < 128) ? (Wx + (size_t)n * HID + q * 4)
                                             : (Wh + (size_t)n * HID + (q - 128) * 4);
                *(float4*)&Ws1[n * W1PAD + q * 4] = *(const float4*)src;
            }
        }

        const int bl = tid >> 3, ul = tid & 7, gc = ul * 4;   // one (b,u) per thread per m-half
        const float4 biasq = *(const float4*)(g_biasP[1] + c * CCOLS + gc);
        const int u = c * 8 + ul;
        float cstA = 0.0f, cstB = 0.0f;

        grid_barrier_round(++round);            // zero-init visible

        for (int r = 0; r < SEQ + 1; r++) {
            if (r >= 1) {
                const int t = r - 1;
                const float* h0read = g_hbuf0[(t & 1) ^ 1];   // h0[t], written by L0 at round t
                const float* h1read = g_hbuf1[t & 1];         // h1[t-1]
                float*       hwrite = g_hbuf1[(t & 1) ^ 1];

#pragma unroll
                for (int mh2 = 0; mh2 < 2; mh2++) {
                    const int rb = mh2 * 32;

                    wmma::fragment<wmma::accumulator, 16, 16, 8, float> acc[2];
                    wmma::fill_fragment(acc[0], 0.0f);
                    wmma::fill_fragment(acc[1], 0.0f);

#pragma unroll
                    for (int pass = 0; pass < 2; pass++) {
                        const float* src = pass ? h1read : h0read;
                        {   // warp-local stage: rows rb+mhw*16..+16, cols kq*128..+128
                            const float* s = src + (size_t)(rb + mhw * 16) * HID + kq * 128 + lane * 4;
                            float* dst = &As1[(mhw * 16) * APAD + kq * 128 + lane * 4];
#pragma unroll
                            for (int i = 0; i < 16; i++)
                                *(float4*)(dst + i * APAD) = __ldcg((const float4*)(s + (size_t)i * HID));
                        }
                        __syncwarp();

                        const float* Abase = &As1[(mhw * 16) * APAD + kq * 128];
                        const float* Bbase = &Ws1[pass * 512 + kq * 128];
#pragma unroll
                        for (int ks = 0; ks < 16; ks++) {
                            wmma::fragment<wmma::matrix_a, 16, 16, 8, wmma::precision::tf32, wmma::row_major> af;
                            wmma::fragment<wmma::matrix_b, 16, 16, 8, wmma::precision::tf32, wmma::col_major> bf[2];
                            wmma::load_matrix_sync(af, Abase + ks * 8, APAD);
#pragma unroll
                            for (int j = 0; j < 2; j++)
                                wmma::load_matrix_sync(bf[j], Bbase + j * 16 * W1PAD + ks * 8, W1PAD);
#pragma unroll
                            for (int j = 0; j < 2; j++) wmma::mma_sync(acc[j], af, bf[j], acc[j]);
                        }
                        __syncwarp();
                    }
                    __syncthreads();   // all warps done with As1 before sg alias write
#pragma unroll
                    for (int j = 0; j < 2; j++)
                        wmma::store_matrix_sync(&sg[kq * (32 * SGP) + (mhw * 16) * SGP + j * 16],
                                                acc[j], SGP, wmma::mem_row_major);
                    __syncthreads();

                    {   // elementwise for 32 batches
                        float4 s0 = *(const float4*)&sg[0 * (32 * SGP) + bl * SGP + gc];
                        float4 s1 = *(const float4*)&sg[1 * (32 * SGP) + bl * SGP + gc];
                        float4 s2 = *(const float4*)&sg[2 * (32 * SGP) + bl * SGP + gc];
                        float4 s3 = *(const float4*)&sg[3 * (32 * SGP) + bl * SGP + gc];
                        float pi = s0.x + s1.x + s2.x + s3.x + biasq.x;
                        float pf = s0.y + s1.y + s2.y + s3.y + biasq.y;
                        float pg = s0.z + s1.z + s2.z + s3.z + biasq.z;
                        float po = s0.w + s1.w + s2.w + s3.w + biasq.w;
                        float ig = sigm(pi), fg = sigm(pf), gg = tanhf(pg), og = sigm(po);
                        float& cst = mh2 ? cstB : cstA;
                        cst = fg * cst + ig * gg;
                        hwrite[(rb + bl) * HID + u] = og * tanhf(cst);
                    }
                    __syncthreads();   // elementwise done before next m-half restages As1/sg
                }
            }
            grid_barrier_round(++round);
        }
    }
}

// ---------------- output projection ----------------
__global__ void out_kernel(const float* __restrict__ Wout, const float* __restrict__ bout,
                           float* __restrict__ out)
{
    int b = blockIdx.x;
    int o = threadIdx.x;
    const float* h  = g_hbuf1[0] + b * HID;   // t=511 odd -> final h1 in buffer 0
    const float* wr = Wout + o * HID;
    float acc = bout[o];
#pragma unroll 8
    for (int u = 0; u < HID; u++) acc = fmaf(h[u], wr[u], acc);
    out[b * ODIM + o] = acc;
}

// ---------------- launch ----------------
extern "C" void kernel_launch(void* const* d_in, const int* in_sizes, int n_in,
                              void* d_out, int out_size)
{
    (void)in_sizes; (void)n_in; (void)out_size;
    const float* prim = (const float*)d_in[0];
    const float* aux  = (const float*)d_in[1];
    const float* Wih0 = (const float*)d_in[2];
    const float* Whh0 = (const float*)d_in[3];
    const float* bih0 = (const float*)d_in[4];
    const float* bhh0 = (const float*)d_in[5];
    const float* Wih1 = (const float*)d_in[6];
    const float* Whh1 = (const float*)d_in[7];
    const float* bih1 = (const float*)d_in[8];
    const float* bhh1 = (const float*)d_in[9];
    const float* Wout = (const float*)d_in[10];
    const float* bout = (const float*)d_in[11];
    float* out = (float*)d_out;

    static bool attr_set = false;
    if (!attr_set) {
        cudaFuncSetAttribute(scan_fused, cudaFuncAttributeMaxDynamicSharedMemorySize,
                             SCAN_SMEM_BYTES);
        attr_set = true;
    }

    prep_kernel<<<1024, 256>>>(prim, aux, Wih0, Whh0, bih0, bhh0, Wih1, Whh1, bih1, bhh1);
    gemm_tf32<<<dim3(16, 256), 256>>>();                         // x_proj0
    scan_fused<<<NB_SCAN, NT_SCAN, SCAN_SMEM_BYTES>>>();         // both layers, pipelined
    out_kernel<<<BATCH, ODIM>>>(Wout, bout, out);
}